// round 8
// baseline (speedup 1.0000x reference)
#include <cuda_runtime.h>
#include <cuda_fp16.h>
#include <cstdint>
#include <math.h>

#define DD 128
#define KK 32
#define NMAX 50000

// Scratch (allocation-free rule: __device__ globals)
__device__ float  g_x[NMAX * DD];     // tangent-space features for layer-1 GEMM
__device__ __half g_msg[NMAX * DD];   // GEMM output (messages), fp16

// ---------------------------------------------------------------------------
// cp.async 16B helper (pred=false -> zero-fill)
// ---------------------------------------------------------------------------
__device__ __forceinline__ void cp16(void* dst_smem, const void* src, bool pred) {
    unsigned sdst = (unsigned)__cvta_generic_to_shared(dst_smem);
    int sz = pred ? 16 : 0;
    asm volatile("cp.async.cg.shared.global [%0], [%1], 16, %2;\n"
                 :: "r"(sdst), "l"(src), "r"(sz));
}

// ---------------------------------------------------------------------------
// Tensor-core GEMM: C[N,128] = A @ W[128,128], epilogue * mask^MPOW, fp16 out.
// mma.sync.m16n8k8 tf32, fp32 accumulate. 2-stage cp.async pipeline, BK=16.
// 256 threads = 8 warps as 4(row) x 2(col); warp tile 32x64 = 2x8 atoms.
// ---------------------------------------------------------------------------
#define BK 16
#define SA 20
#define SW 136

template <int MPOW>
__global__ __launch_bounds__(256, 2)
void gemm_tc_kernel(const float* __restrict__ A,
                    const float* __restrict__ W,
                    const float* __restrict__ mask,
                    __half* __restrict__ C,
                    int N) {
    __shared__ float As[2][128 * SA];
    __shared__ float Ws[2][BK * SW];

    int tid  = threadIdx.x;
    int lane = tid & 31;
    int warp = tid >> 5;
    int wr   = warp >> 1;
    int wc   = warp & 1;
    int g    = lane >> 2;
    int tg   = lane & 3;

    int block_row = blockIdx.x * 128;

    float acc[2][8][4];
    #pragma unroll
    for (int ma = 0; ma < 2; ma++)
        #pragma unroll
        for (int na = 0; na < 8; na++)
            #pragma unroll
            for (int i = 0; i < 4; i++) acc[ma][na][i] = 0.f;

    #define LOAD_TILES(s, k0)                                                  \
    {                                                                          \
        _Pragma("unroll")                                                      \
        for (int i = 0; i < 2; i++) {                                          \
            int idx  = tid + i * 256;                                          \
            int row  = idx >> 2;                                               \
            int c4   = idx & 3;                                                \
            int grow = block_row + row;                                        \
            cp16(&As[s][row * SA + c4 * 4],                                    \
                 A + (size_t)grow * 128 + (k0) + c4 * 4, grow < N);            \
        }                                                                      \
        _Pragma("unroll")                                                      \
        for (int i = 0; i < 2; i++) {                                          \
            int idx = tid + i * 256;                                           \
            int kr  = idx >> 5;                                                \
            int c4  = idx & 31;                                                \
            cp16(&Ws[s][kr * SW + c4 * 4],                                     \
                 W + (size_t)((k0) + kr) * 128 + c4 * 4, true);                \
        }                                                                      \
        asm volatile("cp.async.commit_group;\n");                              \
    }

    LOAD_TILES(0, 0);

    #pragma unroll
    for (int it = 0; it < 8; it++) {
        int s = it & 1;
        if (it < 7) LOAD_TILES(s ^ 1, (it + 1) * BK);
        if (it < 7) asm volatile("cp.async.wait_group 1;\n");
        else        asm volatile("cp.async.wait_group 0;\n");
        __syncthreads();

        #pragma unroll
        for (int ks = 0; ks < 2; ks++) {
            int k8 = ks * 8;
            unsigned int af[2][4];
            #pragma unroll
            for (int ma = 0; ma < 2; ma++) {
                int r = wr * 32 + ma * 16;
                const unsigned int* Asu = (const unsigned int*)As[s];
                af[ma][0] = Asu[(r + g)     * SA + k8 + tg];
                af[ma][1] = Asu[(r + g + 8) * SA + k8 + tg];
                af[ma][2] = Asu[(r + g)     * SA + k8 + tg + 4];
                af[ma][3] = Asu[(r + g + 8) * SA + k8 + tg + 4];
            }
            unsigned int bf[8][2];
            #pragma unroll
            for (int na = 0; na < 8; na++) {
                int cc = wc * 64 + na * 8 + g;
                const unsigned int* Wsu = (const unsigned int*)Ws[s];
                bf[na][0] = Wsu[(k8 + tg)     * SW + cc];
                bf[na][1] = Wsu[(k8 + tg + 4) * SW + cc];
            }
            #pragma unroll
            for (int ma = 0; ma < 2; ma++)
                #pragma unroll
                for (int na = 0; na < 8; na++) {
                    asm volatile(
                        "mma.sync.aligned.m16n8k8.row.col.f32.tf32.tf32.f32 "
                        "{%0,%1,%2,%3}, {%4,%5,%6,%7}, {%8,%9}, {%0,%1,%2,%3};\n"
                        : "+f"(acc[ma][na][0]), "+f"(acc[ma][na][1]),
                          "+f"(acc[ma][na][2]), "+f"(acc[ma][na][3])
                        : "r"(af[ma][0]), "r"(af[ma][1]),
                          "r"(af[ma][2]), "r"(af[ma][3]),
                          "r"(bf[na][0]), "r"(bf[na][1]));
                }
        }
        __syncthreads();
    }

    #pragma unroll
    for (int ma = 0; ma < 2; ma++) {
        int r0g = block_row + wr * 32 + ma * 16 + g;
        int r1g = r0g + 8;
        float m0 = (r0g < N) ? mask[r0g] : 0.f;
        float m1 = (r1g < N) ? mask[r1g] : 0.f;
        if (MPOW == 2) { m0 *= m0; m1 *= m1; }
        #pragma unroll
        for (int na = 0; na < 8; na++) {
            int col = wc * 64 + na * 8 + 2 * tg;
            if (r0g < N) {
                __half2 h = __floats2half2_rn(acc[ma][na][0] * m0,
                                              acc[ma][na][1] * m0);
                *(__half2*)(C + (size_t)r0g * 128 + col) = h;
            }
            if (r1g < N) {
                __half2 h = __floats2half2_rn(acc[ma][na][2] * m1,
                                              acc[ma][na][3] * m1);
                *(__half2*)(C + (size_t)r1g * 128 + col) = h;
            }
        }
    }
}

// ---------------------------------------------------------------------------
// Gather v3: 2 nodes per warp, 16 lanes per node, 8 columns per lane,
// explicit 4-deep LDG prefetch pipeline (buf[4] of uint4 + wbuf[4]) to keep
// 4 independent LDG.128 in flight per thread and hide L2 latency.
// ---------------------------------------------------------------------------
#define PF 4

template <bool FUSE_LOGMAP>
__global__ __launch_bounds__(256)
void gather_kernel(const int*    __restrict__ adj,
                   const float*  __restrict__ wgt,
                   const float*  __restrict__ mask,
                   const __half* __restrict__ msg,
                   float* __restrict__ xout,
                   int N) {
    __shared__ int2 pairs[8][2][KK];    // [warp][node-half][k]

    int tid   = threadIdx.x;
    int warp  = tid >> 5;
    int lane  = tid & 31;
    int half  = lane >> 4;              // which node within warp
    int hl    = lane & 15;              // lane within node (owns 8 cols)
    int node0 = blockIdx.x * 16 + warp * 2;
    int gnode = node0 + half;

    // stage both nodes' (adj, w) rows: 64 pairs per warp, 2 per lane
    #pragma unroll
    for (int i = 0; i < 2; i++) {
        int idx = lane + i * 32;        // 0..63
        int h   = idx >> 5;
        int k   = idx & 31;
        int gn  = node0 + h;
        if (gn < N) {
            pairs[warp][h][k].x = adj[(size_t)gn * KK + k];
            pairs[warp][h][k].y = __float_as_int(wgt[(size_t)gn * KK + k]);
        }
    }
    __syncwarp();
    if (gnode >= N) return;

    const __half* mrow = msg + hl * 8;

    // prime the pipeline: PF rows in flight
    uint4 buf[PF];
    float wbuf[PF];
    #pragma unroll
    for (int k = 0; k < PF; k++) {
        int2 p = pairs[warp][half][k];
        wbuf[k] = __int_as_float(p.y);
        buf[k]  = *(const uint4*)(mrow + (size_t)p.x * DD);
    }

    float acc[8];
    #pragma unroll
    for (int i = 0; i < 8; i++) acc[i] = 0.f;

    #pragma unroll
    for (int k = 0; k < KK; k++) {
        uint4 raw = buf[k & (PF - 1)];
        float wk  = wbuf[k & (PF - 1)];
        if (k + PF < KK) {
            int2 p = pairs[warp][half][k + PF];
            wbuf[k & (PF - 1)] = __int_as_float(p.y);
            buf[k & (PF - 1)]  = *(const uint4*)(mrow + (size_t)p.x * DD);
        }
        float2 f0 = __half22float2(*(__half2*)&raw.x);
        float2 f1 = __half22float2(*(__half2*)&raw.y);
        float2 f2 = __half22float2(*(__half2*)&raw.z);
        float2 f3 = __half22float2(*(__half2*)&raw.w);
        acc[0] = fmaf(wk, f0.x, acc[0]);
        acc[1] = fmaf(wk, f0.y, acc[1]);
        acc[2] = fmaf(wk, f1.x, acc[2]);
        acc[3] = fmaf(wk, f1.y, acc[3]);
        acc[4] = fmaf(wk, f2.x, acc[4]);
        acc[5] = fmaf(wk, f2.y, acc[5]);
        acc[6] = fmaf(wk, f3.x, acc[6]);
        acc[7] = fmaf(wk, f3.y, acc[7]);
    }

    float mk = mask[gnode];
    #pragma unroll
    for (int i = 0; i < 8; i++) acc[i] *= mk;     // combined

    // exp-map at origin (norm over this node's 16 lanes x 8 cols)
    float s = 0.f;
    #pragma unroll
    for (int i = 0; i < 8; i++) s = fmaf(acc[i], acc[i], s);
    #pragma unroll
    for (int o = 8; o > 0; o >>= 1) s += __shfl_xor_sync(0xffffffffu, s, o);
    float n  = sqrtf(s);
    float nc = fminf(fmaxf(n, 1e-5f), 15.0f);
    float scale = tanhf(nc) / fmaxf(n, 1e-5f) * mk;   // expmap * mask

    float x[8];
    #pragma unroll
    for (int i = 0; i < 8; i++) x[i] = fmaxf(acc[i] * scale, 0.f) * mk;

    if (FUSE_LOGMAP) {
        float s2 = 0.f;
        #pragma unroll
        for (int i = 0; i < 8; i++) s2 = fmaf(x[i], x[i], s2);
        #pragma unroll
        for (int o = 8; o > 0; o >>= 1) s2 += __shfl_xor_sync(0xffffffffu, s2, o);
        float n2  = sqrtf(s2);
        float nc2 = fminf(fmaxf(n2, 1e-5f), 1.0f - 1e-5f);
        float ls  = atanhf(nc2) / fmaxf(n2, 1e-5f) * mk;
        #pragma unroll
        for (int i = 0; i < 8; i++) x[i] *= ls;
    }

    float* dst = xout + (size_t)gnode * DD + hl * 8;
    *(float4*)(dst)     = make_float4(x[0], x[1], x[2], x[3]);
    *(float4*)(dst + 4) = make_float4(x[4], x[5], x[6], x[7]);
}

// ---------------------------------------------------------------------------
extern "C" void kernel_launch(void* const* d_in, const int* in_sizes, int n_in,
                              void* d_out, int out_size) {
    const float* node_repr = (const float*)d_in[0];
    const int*   adj       = (const int*)  d_in[1];
    const float* weight    = (const float*)d_in[2];
    const float* mask      = (const float*)d_in[3];
    const float* msg_w     = (const float*)d_in[4];

    int N = in_sizes[0] / DD;
    float* out = (float*)d_out;

    float*  xbuf;
    __half* mbuf;
    cudaGetSymbolAddress((void**)&xbuf, g_x);
    cudaGetSymbolAddress((void**)&mbuf, g_msg);

    int gatherBlocks = (N + 15) / 16;       // 16 nodes per 256-thread block
    int gemmBlocks   = (N + 127) / 128;

    // ---- Layer 0 ----  ((x*m)@W*m = m^2*(x@W): mask^2 in epilogue)
    gemm_tc_kernel<2><<<gemmBlocks, 256>>>(node_repr, msg_w, mask, mbuf, N);
    gather_kernel<true><<<gatherBlocks, 256>>>(adj, weight, mask, mbuf, xbuf, N);

    // ---- Layer 1 ----  (xbuf already tangent-space * mask)
    gemm_tc_kernel<1><<<gemmBlocks, 256>>>(xbuf, msg_w + DD * DD, mask, mbuf, N);
    gather_kernel<false><<<gatherBlocks, 256>>>(adj, weight, mask, mbuf, out, N);
}